// round 13
// baseline (speedup 1.0000x reference)
#include <cuda_runtime.h>
#include <cuda_fp16.h>
#include <stdint.h>

// out[r,o] = tanh(scale(r) * dot(enc_row(r), W[o,:]) + b[o])
//   r = b*128 + m (m = l*4+n, l<32) -> M=4096 ; enc phys row = b*2048 + m
//   K=256, N=256. (Spectral DCT/mask/IDCT collapses to mask*enc since the
//   band mask is independent of the DCT index.)
//
// fp16 HMMA m16n8k16, fp32 accum; BOTH A and B single fp16 (products exact
// in fp32; only input rounding ~2^-11 each -> rel err ~3.5e-4 < 1e-3;
// A-only was measured 2.2e-4).
//
// Round 13: prefetch-distance-2 software pipeline over 4 K-chunks of 64:
//   pre:  P(0,b0) C(0,b0) P(1,b1) sync
//   c:    P(c+2)  MMA(c)  C(c+1)  sync
// commit(c+1) consumes LDGs issued a full iteration earlier -> L2 latency
// fully hidden (R11/12 had distance ~1 MMA block < latency). smem 96KB
// (A 64 + B 32), 512 thr = 16 warps 4(M:32)x4(N:16), grid (32,4) = 1 wave.

#define THREADS 512
#define OFF_A 0
#define OFF_B 65536
#define DYN_SMEM 98304

static __device__ __forceinline__ uint32_t smem_u32(const void* p) {
    uint32_t a;
    asm("{ .reg .u64 t; cvta.to.shared.u64 t, %1; cvt.u32.u64 %0, t; }"
        : "=r"(a) : "l"(p));
    return a;
}

static __device__ __forceinline__ void ldmx4(uint32_t* r, uint32_t addr) {
    asm volatile("ldmatrix.sync.aligned.m8n8.x4.shared.b16 {%0,%1,%2,%3}, [%4];"
                 : "=r"(r[0]), "=r"(r[1]), "=r"(r[2]), "=r"(r[3]) : "r"(addr));
}

static __device__ __forceinline__ void mma16816(float* c, const uint32_t* a,
                                                uint32_t b0, uint32_t b1) {
    asm volatile(
        "mma.sync.aligned.m16n8k16.row.col.f32.f16.f16.f32 "
        "{%0,%1,%2,%3},{%4,%5,%6,%7},{%8,%9},{%0,%1,%2,%3};"
        : "+f"(c[0]), "+f"(c[1]), "+f"(c[2]), "+f"(c[3])
        : "r"(a[0]), "r"(a[1]), "r"(a[2]), "r"(a[3]), "r"(b0), "r"(b1));
}

static __device__ __forceinline__ float tanh_fast(float x) {
    float e = __expf(2.0f * x);
    return 1.0f - __fdividef(2.0f, e + 1.0f);
}

static __device__ __forceinline__ uint4 cvt8_h(const float4& v0, const float4& v1) {
    __half2 h0 = __floats2half2_rn(v0.x, v0.y);
    __half2 h1 = __floats2half2_rn(v0.z, v0.w);
    __half2 h2 = __floats2half2_rn(v1.x, v1.y);
    __half2 h3 = __floats2half2_rn(v1.z, v1.w);
    return make_uint4(*(uint32_t*)&h0, *(uint32_t*)&h1,
                      *(uint32_t*)&h2, *(uint32_t*)&h3);
}

__global__ __launch_bounds__(THREADS, 1) void spectral_hmma_kernel(
    const float* __restrict__ enc,
    const float* __restrict__ W,
    const float* __restrict__ bias,
    float* __restrict__ out)
{
    extern __shared__ __align__(16) uint8_t dyn[];
    const uint32_t sbase = smem_u32(dyn);

    const int tid = threadIdx.x;
    const int wid = tid >> 5;
    const int lid = tid & 31;
    const int bx = blockIdx.x;   // batch (M=128 rows), 0..31
    const int by = blockIdx.y;   // N tile (64 cols), 0..3

    const float4* __restrict__ encv = (const float4*)enc;
    const float4* __restrict__ Wv   = (const float4*)W;

    // per-thread chunk-load geometry (A: 1024 16B-units/chunk, B: 512)
    int aRowL[2], aCkl[2];
    #pragma unroll
    for (int s = 0; s < 2; ++s) {
        int g = tid + s * 512;
        aRowL[s] = g >> 3;              // 0..127
        aCkl[s]  = g & 7;
    }
    const int bRowL = tid >> 3;         // 0..63
    const int bCkl  = tid & 7;

    float4 sa[2][2][2], sbuf[2][2];     // double-buffered register staging

    auto prefetch = [&](int c, int pb) {
        #pragma unroll
        for (int s = 0; s < 2; ++s) {
            const float4* p = encv
                + ((size_t)(bx * 2048 + aRowL[s])) * 64 + (c * 8 + aCkl[s]) * 2;
            sa[pb][s][0] = p[0]; sa[pb][s][1] = p[1];
        }
        const float4* p = Wv
            + ((size_t)(by * 64 + bRowL)) * 64 + (c * 8 + bCkl) * 2;
        sbuf[pb][0] = p[0]; sbuf[pb][1] = p[1];
    };

    auto commit = [&](int c, int pb) {
        #pragma unroll
        for (int s = 0; s < 2; ++s) {
            int row = aRowL[s], ck = c * 8 + aCkl[s];
            uint32_t sw = row * 512 + (((ck ^ (row & 7)) & 31) << 4);
            *(uint4*)(dyn + OFF_A + sw) = cvt8_h(sa[pb][s][0], sa[pb][s][1]);
        }
        int ck = c * 8 + bCkl;
        uint32_t sw = bRowL * 512 + (((ck ^ (bRowL & 7)) & 31) << 4);
        *(uint4*)(dyn + OFF_B + sw) = cvt8_h(sbuf[pb][0], sbuf[pb][1]);
    };

    // ---- warp tiling: 16 warps = 4(M: 32 rows) x 4(N: 16 cols)
    const int wm = wid >> 2;
    const int wn = wid & 3;
    const int rl = lid & 15;
    const int kadd = lid >> 4;

    const int aR0 = wm * 32 + rl, aR1 = aR0 + 16;
    const uint32_t aO0 = aR0 * 512, aO1 = aR1 * 512;
    const int ax0 = aR0 & 7, ax1 = aR1 & 7;
    const int bR = wn * 16 + rl;
    const uint32_t bO = bR * 512;
    const int bxr = bR & 7;

    float acc[2][2][4];
    #pragma unroll
    for (int i = 0; i < 2; ++i)
        #pragma unroll
        for (int j = 0; j < 2; ++j)
            #pragma unroll
            for (int q = 0; q < 4; ++q)
                acc[i][j][q] = 0.f;

    // ---- prologue: chunk0 exposed once; chunk1 LDGs in flight
    prefetch(0, 0);
    commit(0, 0);
    prefetch(1, 1);
    __syncthreads();

    for (int c = 0; c < 4; ++c) {
        if (c < 2) prefetch(c + 2, c & 1);

        #pragma unroll
        for (int i = 0; i < 4; ++i) {
            const int ch = (c * 4 + i) * 2 + kadd;
            uint32_t a0[4], a1[4], b[4];
            ldmx4(a0, sbase + OFF_A + aO0 + (((ch ^ ax0) & 31) << 4));
            ldmx4(a1, sbase + OFF_A + aO1 + (((ch ^ ax1) & 31) << 4));
            ldmx4(b,  sbase + OFF_B + bO  + (((ch ^ bxr) & 31) << 4));
            mma16816(acc[0][0], a0, b[0], b[2]);
            mma16816(acc[0][1], a0, b[1], b[3]);
            mma16816(acc[1][0], a1, b[0], b[2]);
            mma16816(acc[1][1], a1, b[1], b[3]);
        }

        if (c < 3) {
            commit(c + 1, (c + 1) & 1);
            __syncthreads();
        }
    }

    // ---- epilogue: band scale, bias, tanh, store
    const int qr = lid >> 2;
    const int qc = (lid & 3) * 2;
    #pragma unroll
    for (int mt = 0; mt < 2; ++mt) {
        #pragma unroll
        for (int h = 0; h < 2; ++h) {
            const int m = wm * 32 + mt * 16 + h * 8 + qr;   // 0..127
            const int n = m & 3, ls = m >> 2;
            const float scale = (n == 0) ? 1.0f
                              : (n == 1) ? ((ls < 16) ? 0.1f : 1.0f)
                              : 0.1f;
            float* orow = out + ((size_t)(bx * 128 + m)) * 256
                              + by * 64 + wn * 16 + qc;
            const float* brow = bias + by * 64 + wn * 16 + qc;
            #pragma unroll
            for (int nt = 0; nt < 2; ++nt) {
                float2 bb = *(const float2*)(brow + nt * 8);
                float2 o;
                o.x = tanh_fast(fmaf(scale, acc[mt][nt][h * 2 + 0], bb.x));
                o.y = tanh_fast(fmaf(scale, acc[mt][nt][h * 2 + 1], bb.y));
                *(float2*)(orow + nt * 8) = o;
            }
        }
    }
}

extern "C" void kernel_launch(void* const* d_in, const int* in_sizes, int n_in,
                              void* d_out, int out_size) {
    const float* enc  = (const float*)d_in[0];
    const float* W    = (const float*)d_in[1];
    const float* bias = (const float*)d_in[2];
    float* out = (float*)d_out;

    cudaFuncSetAttribute(spectral_hmma_kernel,
                         cudaFuncAttributeMaxDynamicSharedMemorySize, DYN_SMEM);
    dim3 grid(32, 4);
    spectral_hmma_kernel<<<grid, THREADS, DYN_SMEM>>>(enc, W, bias, out);
}